// round 4
// baseline (speedup 1.0000x reference)
#include <cuda_runtime.h>
#include <math.h>

#define NB   100
#define NPG  500
#define NN   (NB*NPG)     // 50000 nodes
#define NE   (NN*12)      // 600000 edges
#define EPG  (NPG*12)     // 6000 edges per graph (contiguous)
#define H    128
#define K1   250
#define K2   125
#define K3   63

// ---------------- scratch (device globals; no allocation) ----------------
__device__ float g_h    [NN*H];        // pre-pool features
__device__ float g_mean [NN*H];        // gathered mean
__device__ float g_p1   [NB*K1*H];     // pooled buffer A
__device__ float g_p2   [NB*K2*H];     // pooled buffer B
__device__ int   g_srcB [NE];
__device__ int   g_dstB [NE];
__device__ int   g_srcC [NE];
__device__ int   g_dstC [NE];
__device__ int   g_gecB [NB];
__device__ int   g_gecC [NB];
__device__ float g_z    [NB*2*H];

// ---------------- f32x2 helpers ----------------
__device__ __forceinline__ unsigned long long pk2(float x, float y) {
    unsigned long long r;
    asm("mov.b64 %0, {%1, %2};" : "=l"(r) : "r"(__float_as_uint(x)), "r"(__float_as_uint(y)));
    return r;
}
__device__ __forceinline__ void upk2(unsigned long long v, float& x, float& y) {
    unsigned a, b;
    asm("mov.b64 {%0, %1}, %2;" : "=r"(a), "=r"(b) : "l"(v));
    x = __uint_as_float(a); y = __uint_as_float(b);
}
#define FMA2(d, a, b) asm("fma.rn.f32x2 %0, %1, %2, %0;" : "+l"(d) : "l"(a), "l"(b))

// ---------------- kernels ----------------

// One block per graph: smem degree count -> smem scan -> smem CSR fill ->
// gather neighbor means.
__global__ void __launch_bounds__(512) k_aggregate(
        const int* __restrict__ src, const int* __restrict__ dst,
        const int* __restrict__ gec, int fixed,
        const float* __restrict__ xin, int n_per) {
    extern __shared__ int sm[];
    int* s_src = sm;                 // [EPG]
    int* s_dst = sm + EPG;           // [EPG] (local dst)
    int* s_csr = sm + 2 * EPG;       // [EPG]
    int* s_deg = sm + 3 * EPG;       // [512]
    int* s_st  = s_deg + 512;        // [512] exclusive starts
    int* s_cur = s_st + 512;         // [512] fill cursors

    int b = blockIdx.x, t = threadIdx.x;
    int ne    = fixed ? EPG : gec[b];
    int ebase = b * EPG;
    int nbase = b * n_per;

    s_deg[t] = 0;
    __syncthreads();

    for (int i = t; i < ne; i += blockDim.x) {
        int s = src[ebase + i];
        int d = dst[ebase + i] - nbase;
        s_src[i] = s;
        s_dst[i] = d;
        atomicAdd(&s_deg[d], 1);
    }
    __syncthreads();

    // Hillis-Steele inclusive scan over 512 entries
    int v = s_deg[t];
    s_st[t] = v;
    __syncthreads();
    #pragma unroll
    for (int o = 1; o < 512; o <<= 1) {
        int u = (t >= o) ? s_st[t - o] : 0;
        __syncthreads();
        s_st[t] += u;
        __syncthreads();
    }
    int excl = s_st[t] - v;
    s_st[t]  = excl;
    s_cur[t] = excl;
    __syncthreads();

    for (int i = t; i < ne; i += blockDim.x) {
        int pos = atomicAdd(&s_cur[s_dst[i]], 1);
        s_csr[pos] = s_src[i];
    }
    __syncthreads();

    // gather: warp per node
    int lane = t & 31, wid = t >> 5, nw = blockDim.x >> 5;
    for (int node = wid; node < n_per; node += nw) {
        int deg = s_deg[node], st = s_st[node];
        float4 acc = {0.f, 0.f, 0.f, 0.f};
        for (int j = 0; j < deg; j++) {
            int s = s_csr[st + j];
            float4 vv = reinterpret_cast<const float4*>(xin + (size_t)s * H)[lane];
            acc.x += vv.x; acc.y += vv.y; acc.z += vv.z; acc.w += vv.w;
        }
        float invd = 1.0f / fmaxf((float)deg, 1.0f);
        acc.x *= invd; acc.y *= invd; acc.z *= invd; acc.w *= invd;
        reinterpret_cast<float4*>(g_mean + (size_t)(nbase + node) * H)[lane] = acc;
    }
}

// out = relu( [mean||x] @ [Wl;Wr] + bl )
// K=256 fused GEMM done in two K-phases (mean cols then x cols).
// A-tile stored pre-duplicated as f32x2 pairs so the FFMA2 inner loop has
// ZERO packing MOVs: every operand comes straight from LDS.128.
#define TM 64
__global__ void __launch_bounds__(256) k_sage(const float* __restrict__ xin,
                                              const float* __restrict__ Wl,
                                              const float* __restrict__ bl,
                                              const float* __restrict__ Wr,
                                              float* __restrict__ out, int n) {
    extern __shared__ float sh[];
    float* sW = sh;                                                  // [256][128]
    unsigned long long* sA = (unsigned long long*)(sh + 256 * 128);  // [64][128] dup pairs
    float* sb = (float*)(sA + 64 * 128);                             // [128]
    int t = threadIdx.x;
    for (int i = t; i < 128 * 128; i += 256) { sW[i] = Wl[i]; sW[128 * 128 + i] = Wr[i]; }
    if (t < 128) sb[t] = bl[t];
    __syncthreads();

    int tx = t & 31, ty = t >> 5;
    int ntiles = (n + TM - 1) / TM;

    for (int tile = blockIdx.x; tile < ntiles; tile += gridDim.x) {
        int row0 = tile * TM;

        unsigned long long acc[8][2];
        #pragma unroll
        for (int i = 0; i < 8; i++) { acc[i][0] = 0ULL; acc[i][1] = 0ULL; }

        #pragma unroll
        for (int ph = 0; ph < 2; ph++) {
            const float* srcmat = ph ? xin : g_mean;
            __syncthreads();             // previous phase readers done
            // load 64 rows x 128 cols, duplicated into f32x2 pairs
            for (int i = t; i < 64 * 32; i += 256) {
                int r = i >> 5, c4 = i & 31;
                int grow = row0 + r;
                float4 v = {0.f, 0.f, 0.f, 0.f};
                if (grow < n)
                    v = *reinterpret_cast<const float4*>(srcmat + (size_t)grow * H + c4 * 4);
                unsigned long long* dp = sA + r * 128 + c4 * 4;
                dp[0] = pk2(v.x, v.x);
                dp[1] = pk2(v.y, v.y);
                dp[2] = pk2(v.z, v.z);
                dp[3] = pk2(v.w, v.w);
            }
            __syncthreads();

            const float* wbase = sW + ph * 128 * 128;
            #pragma unroll 4
            for (int k = 0; k < 128; k += 2) {
                longlong2 w0 = *reinterpret_cast<const longlong2*>(wbase + k * 128 + tx * 4);
                longlong2 w1 = *reinterpret_cast<const longlong2*>(wbase + (k + 1) * 128 + tx * 4);
                #pragma unroll
                for (int i = 0; i < 8; i++) {
                    int r = ty + (i << 3);
                    ulonglong2 a = *reinterpret_cast<const ulonglong2*>(sA + r * 128 + k);
                    FMA2(acc[i][0], a.x, (unsigned long long)w0.x);
                    FMA2(acc[i][1], a.x, (unsigned long long)w0.y);
                    FMA2(acc[i][0], a.y, (unsigned long long)w1.x);
                    FMA2(acc[i][1], a.y, (unsigned long long)w1.y);
                }
            }
        }

        float b0 = sb[tx * 4 + 0], b1 = sb[tx * 4 + 1], b2 = sb[tx * 4 + 2], b3 = sb[tx * 4 + 3];
        #pragma unroll
        for (int i = 0; i < 8; i++) {
            int r = row0 + ty + (i << 3);
            if (r < n) {
                float x0, x1, x2, x3;
                upk2(acc[i][0], x0, x1);
                upk2(acc[i][1], x2, x3);
                float4 o;
                o.x = fmaxf(x0 + b0, 0.f);
                o.y = fmaxf(x1 + b1, 0.f);
                o.z = fmaxf(x2 + b2, 0.f);
                o.w = fmaxf(x3 + b3, 0.f);
                *reinterpret_cast<float4*>(out + (size_t)r * H + tx * 4) = o;
            }
        }
    }
}

// One block per graph: score + stable top-k + pool + readout + edge compact.
__global__ void __launch_bounds__(512) k_pool_all(
        const float* __restrict__ h, const float* __restrict__ pw,
        int n_per, int k, int layer,
        const int* __restrict__ src, const int* __restrict__ dst,
        const int* __restrict__ gec, int fixed,
        int* __restrict__ nsrc, int* __restrict__ ndst, int* __restrict__ ngec,
        float* __restrict__ hout) {
    __shared__ float s_w[128];
    __shared__ float s_sc[512];
    __shared__ int   s_map[512];
    __shared__ int   s_perm[256];
    __shared__ float s_inv;
    __shared__ int   s_cursor;

    int b = blockIdx.x, t = threadIdx.x;
    int lane = t & 31, wid = t >> 5, nw = blockDim.x >> 5;
    int nbase = b * n_per;

    if (t < 128) s_w[t] = pw[t];
    if (t == 0) s_cursor = 0;
    __syncthreads();

    if (wid == 0) {
        float wn = 0.f;
        #pragma unroll
        for (int c = lane; c < 128; c += 32) { float w = s_w[c]; wn += w * w; }
        #pragma unroll
        for (int o = 16; o; o >>= 1) wn += __shfl_down_sync(0xffffffffu, wn, o);
        if (lane == 0) s_inv = rsqrtf(wn);
    }
    __syncthreads();
    float inv = s_inv;

    // scores: warp per node
    for (int node = wid; node < n_per; node += nw) {
        const float* row = h + (size_t)(nbase + node) * H;
        float dot = 0.f;
        #pragma unroll
        for (int c = lane; c < 128; c += 32) dot += row[c] * s_w[c];
        #pragma unroll
        for (int o = 16; o; o >>= 1) dot += __shfl_down_sync(0xffffffffu, dot, o);
        if (lane == 0) s_sc[node] = tanhf(dot * inv);
    }
    __syncthreads();

    // stable top-k via rank counting (matches jax.lax.top_k tie-break)
    if (t < n_per) {
        float si = s_sc[t];
        int rank = 0;
        for (int j = 0; j < n_per; j++) {
            float sj = s_sc[j];
            rank += (sj > si) || (sj == si && j < t);
        }
        if (rank < k) { s_map[t] = rank; s_perm[rank] = t; }
        else          s_map[t] = -1;
    }
    __syncthreads();

    // pool: warp per kept rank
    for (int r = wid; r < k; r += nw) {
        int node = s_perm[r];
        float sc = s_sc[node];
        float4 v = reinterpret_cast<const float4*>(h + (size_t)(nbase + node) * H)[lane];
        v.x *= sc; v.y *= sc; v.z *= sc; v.w *= sc;
        reinterpret_cast<float4*>(hout + (size_t)(b * k + r) * H)[lane] = v;
    }
    __syncthreads();

    // readout: max||mean over k pooled rows
    if (t < 128) {
        float mx = -1e30f, sm = 0.f;
        for (int r = 0; r < k; r++) {
            float v = hout[(size_t)(b * k + r) * H + t];
            mx = fmaxf(mx, v);
            sm += v;
        }
        float mean = sm / (float)k;
        if (layer == 0) {
            g_z[b * 2 * H + t]     = mx;
            g_z[b * 2 * H + H + t] = mean;
        } else {
            g_z[b * 2 * H + t]     += mx;
            g_z[b * 2 * H + H + t] += mean;
        }
    }

    // edge remap + compact into next layer's per-graph region
    if (layer < 2) {
        int ne = fixed ? EPG : gec[b];
        int ebase = b * EPG;
        for (int e0 = 0; e0 < ne; e0 += blockDim.x) {
            int e = e0 + t;
            int rs = -1, rd = -1;
            if (e < ne) {
                rs = s_map[src[ebase + e] - nbase];
                rd = s_map[dst[ebase + e] - nbase];
            }
            bool act = (rs >= 0) && (rd >= 0);
            unsigned m = __ballot_sync(0xffffffffu, act);
            if (m) {
                int leader = __ffs(m) - 1;
                int base = 0;
                if (lane == leader) base = atomicAdd(&s_cursor, __popc(m));
                base = __shfl_sync(0xffffffffu, base, leader);
                if (act) {
                    int pos = base + __popc(m & ((1u << lane) - 1u));
                    nsrc[ebase + pos] = b * k + rs;
                    ndst[ebase + pos] = b * k + rd;
                }
            }
        }
        __syncthreads();
        if (t == 0) ngec[b] = s_cursor;
    }
}

// MLP head + log_softmax, one block per graph
__global__ void k_mlp(const float* __restrict__ W1, const float* __restrict__ b1,
                      const float* __restrict__ W2, const float* __restrict__ b2,
                      const float* __restrict__ W3, const float* __restrict__ b3,
                      float* __restrict__ out) {
    int b = blockIdx.x, t = threadIdx.x;
    __shared__ float zin[256], t1[128], t2[64], lg[10];
    zin[t] = g_z[b * 256 + t];
    __syncthreads();
    if (t < 128) {
        float a = b1[t];
        for (int k = 0; k < 256; k++) a += zin[k] * W1[k * 128 + t];
        t1[t] = fmaxf(a, 0.f);
    }
    __syncthreads();
    if (t < 64) {
        float a = b2[t];
        for (int k = 0; k < 128; k++) a += t1[k] * W2[k * 64 + t];
        t2[t] = fmaxf(a, 0.f);
    }
    __syncthreads();
    if (t < 10) {
        float a = b3[t];
        for (int k = 0; k < 64; k++) a += t2[k] * W3[k * 10 + t];
        lg[t] = a;
    }
    __syncthreads();
    if (t == 0) {
        float mx = -1e30f;
        for (int i = 0; i < 10; i++) mx = fmaxf(mx, lg[i]);
        float s = 0.f;
        for (int i = 0; i < 10; i++) s += expf(lg[i] - mx);
        float lse = mx + logf(s);
        for (int i = 0; i < 10; i++) out[b * 10 + i] = lg[i] - lse;
    }
}

// ---------------- host ----------------

static const int SAGE_SMEM = 256 * 128 * 4 + 64 * 128 * 8 + 128 * 4;  // 197120 B
static const int AGG_SMEM  = (3 * EPG + 3 * 512) * sizeof(int);       // 78144 B

extern "C" void kernel_launch(void* const* d_in, const int* in_sizes, int n_in,
                              void* d_out, int out_size) {
    const float* x   = (const float*)d_in[0];
    const int*   ei  = (const int*)  d_in[1];
    const float* Wl1 = (const float*)d_in[2];
    const float* bl1 = (const float*)d_in[3];
    const float* Wr1 = (const float*)d_in[4];
    const float* Wl2 = (const float*)d_in[5];
    const float* bl2 = (const float*)d_in[6];
    const float* Wr2 = (const float*)d_in[7];
    const float* Wl3 = (const float*)d_in[8];
    const float* bl3 = (const float*)d_in[9];
    const float* Wr3 = (const float*)d_in[10];
    const float* pw1 = (const float*)d_in[11];
    const float* pw2 = (const float*)d_in[12];
    const float* pw3 = (const float*)d_in[13];
    const float* W1  = (const float*)d_in[14];
    const float* b1  = (const float*)d_in[15];
    const float* W2  = (const float*)d_in[16];
    const float* b2  = (const float*)d_in[17];
    const float* W3  = (const float*)d_in[18];
    const float* b3  = (const float*)d_in[19];
    float* out = (float*)d_out;

    static bool attr_set = false;
    if (!attr_set) {
        cudaFuncSetAttribute(k_sage,      cudaFuncAttributeMaxDynamicSharedMemorySize, SAGE_SMEM);
        cudaFuncSetAttribute(k_aggregate, cudaFuncAttributeMaxDynamicSharedMemorySize, AGG_SMEM);
        attr_set = true;
    }

    void *p_h, *p_p1, *p_p2, *p_srcB, *p_dstB, *p_srcC, *p_dstC, *p_gecB, *p_gecC;
    cudaGetSymbolAddress(&p_h,    g_h);
    cudaGetSymbolAddress(&p_p1,   g_p1);
    cudaGetSymbolAddress(&p_p2,   g_p2);
    cudaGetSymbolAddress(&p_srcB, g_srcB);
    cudaGetSymbolAddress(&p_dstB, g_dstB);
    cudaGetSymbolAddress(&p_srcC, g_srcC);
    cudaGetSymbolAddress(&p_dstC, g_dstC);
    cudaGetSymbolAddress(&p_gecB, g_gecB);
    cudaGetSymbolAddress(&p_gecC, g_gecC);
    float* dh = (float*)p_h;

    struct Layer {
        const float *Wl, *bl, *Wr, *pw;
        const int *src, *dst, *gec;   // this layer's edges
        int fixed;
        int *nsrc, *ndst, *ngec;      // next layer's edges
        int n_in, n_per, k;
        float* pool_out;
    } layers[3] = {
        {Wl1, bl1, Wr1, pw1, ei,           ei + NE,      nullptr,       1,
         (int*)p_srcB, (int*)p_dstB, (int*)p_gecB, NN,      NPG, K1, (float*)p_p1},
        {Wl2, bl2, Wr2, pw2, (int*)p_srcB, (int*)p_dstB, (int*)p_gecB,  0,
         (int*)p_srcC, (int*)p_dstC, (int*)p_gecC, NB * K1, K1,  K2, (float*)p_p2},
        {Wl3, bl3, Wr3, pw3, (int*)p_srcC, (int*)p_dstC, (int*)p_gecC,  0,
         nullptr, nullptr, nullptr,                  NB * K2, K2,  K3, (float*)p_p1},
    };

    const float* xin = x;
    for (int l = 0; l < 3; l++) {
        const Layer& L = layers[l];
        int n = L.n_in;

        k_aggregate<<<NB, 512, AGG_SMEM>>>(L.src, L.dst, L.gec, L.fixed, xin, L.n_per);

        int ntiles = (n + TM - 1) / TM;
        int grid = ntiles < 148 ? ntiles : 148;
        k_sage<<<grid, 256, SAGE_SMEM>>>(xin, L.Wl, L.bl, L.Wr, dh, n);

        k_pool_all<<<NB, 512>>>(dh, L.pw, L.n_per, L.k, l,
                                L.src, L.dst, L.gec, L.fixed,
                                L.nsrc, L.ndst, L.ngec, L.pool_out);

        xin = L.pool_out;
    }

    k_mlp<<<NB, 256>>>(W1, b1, W2, b2, W3, b3, out);
}

// round 5
// speedup vs baseline: 1.7295x; 1.7295x over previous
#include <cuda_runtime.h>
#include <math.h>

#define NB   100
#define NPG  500
#define NN   (NB*NPG)     // 50000 nodes
#define NE   (NN*12)      // 600000 edges
#define EPG  (NPG*12)     // 6000 edges per graph (contiguous)
#define H    128
#define K1   250
#define K2   125
#define K3   63

// ---------------- scratch (device globals; no allocation) ----------------
__device__ float g_h    [NN*H];        // pre-pool features
__device__ float g_mean [NN*H];        // gathered mean
__device__ float g_p1   [NB*K1*H];     // pooled buffer A
__device__ float g_p2   [NB*K2*H];     // pooled buffer B
__device__ int   g_srcB [NE];
__device__ int   g_dstB [NE];
__device__ int   g_srcC [NE];
__device__ int   g_dstC [NE];
__device__ int   g_gecB [NB];
__device__ int   g_gecC [NB];
__device__ float g_z    [NB*2*H];

// ---------------- f32x2 helpers ----------------
__device__ __forceinline__ unsigned long long pk2(float x, float y) {
    unsigned long long r;
    asm("mov.b64 %0, {%1, %2};" : "=l"(r) : "r"(__float_as_uint(x)), "r"(__float_as_uint(y)));
    return r;
}
__device__ __forceinline__ void upk2(unsigned long long v, float& x, float& y) {
    unsigned a, b;
    asm("mov.b64 {%0, %1}, %2;" : "=r"(a), "=r"(b) : "l"(v));
    x = __uint_as_float(a); y = __uint_as_float(b);
}
#define FMA2(d, a, b) asm("fma.rn.f32x2 %0, %1, %2, %3;" : "=l"(d) : "l"(a), "l"(b), "l"(d))

// ---------------- kernels ----------------

// One block per graph, 1024 threads: smem degree count -> smem scan ->
// smem CSR fill -> gather neighbor means (unrolled x4 for MLP).
__global__ void __launch_bounds__(1024) k_aggregate(
        const int* __restrict__ src, const int* __restrict__ dst,
        const int* __restrict__ gec, int fixed,
        const float* __restrict__ xin, int n_per) {
    extern __shared__ int sm[];
    int* s_src = sm;                 // [EPG]
    int* s_dst = sm + EPG;           // [EPG] (local dst)
    int* s_csr = sm + 2 * EPG;       // [EPG]
    int* s_deg = sm + 3 * EPG;       // [512]
    int* s_st  = s_deg + 512;        // [512] exclusive starts
    int* s_cur = s_st + 512;         // [512] fill cursors

    int b = blockIdx.x, t = threadIdx.x;
    int ne    = fixed ? EPG : gec[b];
    int ebase = b * EPG;
    int nbase = b * n_per;

    if (t < 512) s_deg[t] = 0;
    __syncthreads();

    for (int i = t; i < ne; i += blockDim.x) {
        int s = src[ebase + i];
        int d = dst[ebase + i] - nbase;
        s_src[i] = s;
        s_dst[i] = d;
        atomicAdd(&s_deg[d], 1);
    }
    __syncthreads();

    // Hillis-Steele inclusive scan over 512 entries (all threads hit syncs)
    int v = (t < 512) ? s_deg[t] : 0;
    if (t < 512) s_st[t] = v;
    __syncthreads();
    #pragma unroll
    for (int o = 1; o < 512; o <<= 1) {
        int u = (t >= o && t < 512) ? s_st[t - o] : 0;
        __syncthreads();
        if (t < 512) s_st[t] += u;
        __syncthreads();
    }
    if (t < 512) {
        int excl = s_st[t] - v;
        s_st[t]  = excl;
        s_cur[t] = excl;
    }
    __syncthreads();

    for (int i = t; i < ne; i += blockDim.x) {
        int pos = atomicAdd(&s_cur[s_dst[i]], 1);
        s_csr[pos] = s_src[i];
    }
    __syncthreads();

    // gather: warp per node, 4 independent accumulator chains
    int lane = t & 31, wid = t >> 5, nw = blockDim.x >> 5;
    for (int node = wid; node < n_per; node += nw) {
        int deg = s_deg[node], st = s_st[node];
        float4 a0 = {0.f,0.f,0.f,0.f}, a1 = a0, a2 = a0, a3 = a0;
        int j = 0;
        for (; j + 4 <= deg; j += 4) {
            int s0 = s_csr[st + j];
            int s1 = s_csr[st + j + 1];
            int s2 = s_csr[st + j + 2];
            int s3 = s_csr[st + j + 3];
            float4 v0 = reinterpret_cast<const float4*>(xin + (size_t)s0 * H)[lane];
            float4 v1 = reinterpret_cast<const float4*>(xin + (size_t)s1 * H)[lane];
            float4 v2 = reinterpret_cast<const float4*>(xin + (size_t)s2 * H)[lane];
            float4 v3 = reinterpret_cast<const float4*>(xin + (size_t)s3 * H)[lane];
            a0.x += v0.x; a0.y += v0.y; a0.z += v0.z; a0.w += v0.w;
            a1.x += v1.x; a1.y += v1.y; a1.z += v1.z; a1.w += v1.w;
            a2.x += v2.x; a2.y += v2.y; a2.z += v2.z; a2.w += v2.w;
            a3.x += v3.x; a3.y += v3.y; a3.z += v3.z; a3.w += v3.w;
        }
        for (; j < deg; j++) {
            int s0 = s_csr[st + j];
            float4 v0 = reinterpret_cast<const float4*>(xin + (size_t)s0 * H)[lane];
            a0.x += v0.x; a0.y += v0.y; a0.z += v0.z; a0.w += v0.w;
        }
        float invd = 1.0f / fmaxf((float)deg, 1.0f);
        float4 o;
        o.x = (a0.x + a1.x + a2.x + a3.x) * invd;
        o.y = (a0.y + a1.y + a2.y + a3.y) * invd;
        o.z = (a0.z + a1.z + a2.z + a3.z) * invd;
        o.w = (a0.w + a1.w + a2.w + a3.w) * invd;
        reinterpret_cast<float4*>(g_mean + (size_t)(nbase + node) * H)[lane] = o;
    }
}

// out = relu( [mean||x] @ [Wl;Wr] + bl ), K=256 fused GEMM, f32x2 packed math
// (R3 version — known good)
#define TM 64
__global__ void __launch_bounds__(256) k_sage(const float* __restrict__ xin,
                                              const float* __restrict__ Wl,
                                              const float* __restrict__ bl,
                                              const float* __restrict__ Wr,
                                              float* __restrict__ out, int n) {
    extern __shared__ float sh[];
    float* sW  = sh;                    // [256][128]
    float* sIn = sh + 256 * 128;        // [64][256]
    float* sb  = sIn + 64 * 256;        // [128]
    int t = threadIdx.x;
    for (int i = t; i < 128 * 128; i += 256) { sW[i] = Wl[i]; sW[128 * 128 + i] = Wr[i]; }
    if (t < 128) sb[t] = bl[t];
    __syncthreads();

    int tx = t & 31, ty = t >> 5;
    int ntiles = (n + TM - 1) / TM;

    for (int tile = blockIdx.x; tile < ntiles; tile += gridDim.x) {
        int row0 = tile * TM;
        __syncthreads();
        for (int i = t; i < 64 * 64; i += 256) {
            int r = i >> 6, c4 = i & 63;
            int grow = row0 + r;
            float4 v = {0.f, 0.f, 0.f, 0.f};
            if (grow < n) {
                const float* src = (c4 < 32)
                    ? (g_mean + (size_t)grow * H + c4 * 4)
                    : (xin    + (size_t)grow * H + (c4 - 32) * 4);
                v = *reinterpret_cast<const float4*>(src);
            }
            *reinterpret_cast<float4*>(sIn + r * 256 + c4 * 4) = v;
        }
        __syncthreads();

        unsigned long long acc[8][2];
        #pragma unroll
        for (int i = 0; i < 8; i++) { acc[i][0] = 0ULL; acc[i][1] = 0ULL; }

        for (int k = 0; k < 256; k += 4) {
            longlong2 w[4];
            #pragma unroll
            for (int kk = 0; kk < 4; kk++)
                w[kk] = *reinterpret_cast<const longlong2*>(sW + (k + kk) * 128 + tx * 4);
            #pragma unroll
            for (int i = 0; i < 8; i++) {
                int r = ty + (i << 3);
                const float4 a = *reinterpret_cast<const float4*>(sIn + r * 256 + k);
                unsigned long long a0 = pk2(a.x, a.x);
                unsigned long long a1 = pk2(a.y, a.y);
                unsigned long long a2 = pk2(a.z, a.z);
                unsigned long long a3 = pk2(a.w, a.w);
                FMA2(acc[i][0], a0, (unsigned long long)w[0].x); FMA2(acc[i][1], a0, (unsigned long long)w[0].y);
                FMA2(acc[i][0], a1, (unsigned long long)w[1].x); FMA2(acc[i][1], a1, (unsigned long long)w[1].y);
                FMA2(acc[i][0], a2, (unsigned long long)w[2].x); FMA2(acc[i][1], a2, (unsigned long long)w[2].y);
                FMA2(acc[i][0], a3, (unsigned long long)w[3].x); FMA2(acc[i][1], a3, (unsigned long long)w[3].y);
            }
        }

        float b0 = sb[tx * 4 + 0], b1 = sb[tx * 4 + 1], b2 = sb[tx * 4 + 2], b3 = sb[tx * 4 + 3];
        #pragma unroll
        for (int i = 0; i < 8; i++) {
            int r = row0 + ty + (i << 3);
            if (r < n) {
                float x0, x1, x2, x3;
                upk2(acc[i][0], x0, x1);
                upk2(acc[i][1], x2, x3);
                float4 o;
                o.x = fmaxf(x0 + b0, 0.f);
                o.y = fmaxf(x1 + b1, 0.f);
                o.z = fmaxf(x2 + b2, 0.f);
                o.w = fmaxf(x3 + b3, 0.f);
                *reinterpret_cast<float4*>(out + (size_t)r * H + tx * 4) = o;
            }
        }
    }
}

// One block per graph: score + stable top-k + pool + readout + edge compact.
__global__ void __launch_bounds__(512) k_pool_all(
        const float* __restrict__ h, const float* __restrict__ pw,
        int n_per, int k, int layer,
        const int* __restrict__ src, const int* __restrict__ dst,
        const int* __restrict__ gec, int fixed,
        int* __restrict__ nsrc, int* __restrict__ ndst, int* __restrict__ ngec,
        float* __restrict__ hout) {
    __shared__ float s_w[128];
    __shared__ float s_sc[512];
    __shared__ int   s_map[512];
    __shared__ int   s_perm[256];
    __shared__ float s_inv;
    __shared__ int   s_cursor;
    __shared__ float s_mx[4][128];
    __shared__ float s_sm[4][128];

    int b = blockIdx.x, t = threadIdx.x;
    int lane = t & 31, wid = t >> 5, nw = blockDim.x >> 5;
    int nbase = b * n_per;

    if (t < 128) s_w[t] = pw[t];
    if (t == 0) s_cursor = 0;
    __syncthreads();

    if (wid == 0) {
        float wn = 0.f;
        #pragma unroll
        for (int c = lane; c < 128; c += 32) { float w = s_w[c]; wn += w * w; }
        #pragma unroll
        for (int o = 16; o; o >>= 1) wn += __shfl_down_sync(0xffffffffu, wn, o);
        if (lane == 0) s_inv = rsqrtf(wn);
    }
    __syncthreads();
    float inv = s_inv;

    // scores: warp per node
    for (int node = wid; node < n_per; node += nw) {
        const float* row = h + (size_t)(nbase + node) * H;
        float dot = 0.f;
        #pragma unroll
        for (int c = lane; c < 128; c += 32) dot += row[c] * s_w[c];
        #pragma unroll
        for (int o = 16; o; o >>= 1) dot += __shfl_down_sync(0xffffffffu, dot, o);
        if (lane == 0) s_sc[node] = tanhf(dot * inv);
    }
    __syncthreads();

    // stable top-k via rank counting (matches jax.lax.top_k tie-break)
    if (t < n_per) {
        float si = s_sc[t];
        int rank = 0;
        for (int j = 0; j < n_per; j++) {
            float sj = s_sc[j];
            rank += (sj > si) || (sj == si && j < t);
        }
        if (rank < k) { s_map[t] = rank; s_perm[rank] = t; }
        else          s_map[t] = -1;
    }
    __syncthreads();

    // pool: warp per kept rank
    for (int r = wid; r < k; r += nw) {
        int node = s_perm[r];
        float sc = s_sc[node];
        float4 v = reinterpret_cast<const float4*>(h + (size_t)(nbase + node) * H)[lane];
        v.x *= sc; v.y *= sc; v.z *= sc; v.w *= sc;
        reinterpret_cast<float4*>(hout + (size_t)(b * k + r) * H)[lane] = v;
    }
    __syncthreads();

    // readout: max||mean over k pooled rows, 4-way parallel over rows
    {
        int q = t >> 7;          // 0..3
        int c = t & 127;
        float mx = -1e30f, smv = 0.f;
        for (int r = q; r < k; r += 4) {
            float v = hout[(size_t)(b * k + r) * H + c];
            mx = fmaxf(mx, v);
            smv += v;
        }
        s_mx[q][c] = mx;
        s_sm[q][c] = smv;
    }
    __syncthreads();
    if (t < 128) {
        float mx = fmaxf(fmaxf(s_mx[0][t], s_mx[1][t]), fmaxf(s_mx[2][t], s_mx[3][t]));
        float smv = s_sm[0][t] + s_sm[1][t] + s_sm[2][t] + s_sm[3][t];
        float mean = smv / (float)k;
        if (layer == 0) {
            g_z[b * 2 * H + t]     = mx;
            g_z[b * 2 * H + H + t] = mean;
        } else {
            g_z[b * 2 * H + t]     += mx;
            g_z[b * 2 * H + H + t] += mean;
        }
    }

    // edge remap + compact into next layer's per-graph region
    if (layer < 2) {
        int ne = fixed ? EPG : gec[b];
        int ebase = b * EPG;
        for (int e0 = 0; e0 < ne; e0 += blockDim.x) {
            int e = e0 + t;
            int rs = -1, rd = -1;
            if (e < ne) {
                rs = s_map[src[ebase + e] - nbase];
                rd = s_map[dst[ebase + e] - nbase];
            }
            bool act = (rs >= 0) && (rd >= 0);
            unsigned m = __ballot_sync(0xffffffffu, act);
            if (m) {
                int leader = __ffs(m) - 1;
                int base = 0;
                if (lane == leader) base = atomicAdd(&s_cursor, __popc(m));
                base = __shfl_sync(0xffffffffu, base, leader);
                if (act) {
                    int pos = base + __popc(m & ((1u << lane) - 1u));
                    nsrc[ebase + pos] = b * k + rs;
                    ndst[ebase + pos] = b * k + rd;
                }
            }
        }
        __syncthreads();
        if (t == 0) ngec[b] = s_cursor;
    }
}

// MLP head + log_softmax, one block per graph
__global__ void k_mlp(const float* __restrict__ W1, const float* __restrict__ b1,
                      const float* __restrict__ W2, const float* __restrict__ b2,
                      const float* __restrict__ W3, const float* __restrict__ b3,
                      float* __restrict__ out) {
    int b = blockIdx.x, t = threadIdx.x;
    __shared__ float zin[256], t1[128], t2[64], lg[10];
    zin[t] = g_z[b * 256 + t];
    __syncthreads();
    if (t < 128) {
        float a = b1[t];
        for (int k = 0; k < 256; k++) a += zin[k] * W1[k * 128 + t];
        t1[t] = fmaxf(a, 0.f);
    }
    __syncthreads();
    if (t < 64) {
        float a = b2[t];
        for (int k = 0; k < 128; k++) a += t1[k] * W2[k * 64 + t];
        t2[t] = fmaxf(a, 0.f);
    }
    __syncthreads();
    if (t < 10) {
        float a = b3[t];
        for (int k = 0; k < 64; k++) a += t2[k] * W3[k * 10 + t];
        lg[t] = a;
    }
    __syncthreads();
    if (t == 0) {
        float mx = -1e30f;
        for (int i = 0; i < 10; i++) mx = fmaxf(mx, lg[i]);
        float s = 0.f;
        for (int i = 0; i < 10; i++) s += expf(lg[i] - mx);
        float lse = mx + logf(s);
        for (int i = 0; i < 10; i++) out[b * 10 + i] = lg[i] - lse;
    }
}

// ---------------- host ----------------

static const int SAGE_SMEM = (256 * 128 + 64 * 256 + 128) * sizeof(float);  // 197120 B
static const int AGG_SMEM  = (3 * EPG + 3 * 512) * sizeof(int);             // 78144 B

extern "C" void kernel_launch(void* const* d_in, const int* in_sizes, int n_in,
                              void* d_out, int out_size) {
    const float* x   = (const float*)d_in[0];
    const int*   ei  = (const int*)  d_in[1];
    const float* Wl1 = (const float*)d_in[2];
    const float* bl1 = (const float*)d_in[3];
    const float* Wr1 = (const float*)d_in[4];
    const float* Wl2 = (const float*)d_in[5];
    const float* bl2 = (const float*)d_in[6];
    const float* Wr2 = (const float*)d_in[7];
    const float* Wl3 = (const float*)d_in[8];
    const float* bl3 = (const float*)d_in[9];
    const float* Wr3 = (const float*)d_in[10];
    const float* pw1 = (const float*)d_in[11];
    const float* pw2 = (const float*)d_in[12];
    const float* pw3 = (const float*)d_in[13];
    const float* W1  = (const float*)d_in[14];
    const float* b1  = (const float*)d_in[15];
    const float* W2  = (const float*)d_in[16];
    const float* b2  = (const float*)d_in[17];
    const float* W3  = (const float*)d_in[18];
    const float* b3  = (const float*)d_in[19];
    float* out = (float*)d_out;

    static bool attr_set = false;
    if (!attr_set) {
        cudaFuncSetAttribute(k_sage,      cudaFuncAttributeMaxDynamicSharedMemorySize, SAGE_SMEM);
        cudaFuncSetAttribute(k_aggregate, cudaFuncAttributeMaxDynamicSharedMemorySize, AGG_SMEM);
        attr_set = true;
    }

    void *p_h, *p_p1, *p_p2, *p_srcB, *p_dstB, *p_srcC, *p_dstC, *p_gecB, *p_gecC;
    cudaGetSymbolAddress(&p_h,    g_h);
    cudaGetSymbolAddress(&p_p1,   g_p1);
    cudaGetSymbolAddress(&p_p2,   g_p2);
    cudaGetSymbolAddress(&p_srcB, g_srcB);
    cudaGetSymbolAddress(&p_dstB, g_dstB);
    cudaGetSymbolAddress(&p_srcC, g_srcC);
    cudaGetSymbolAddress(&p_dstC, g_dstC);
    cudaGetSymbolAddress(&p_gecB, g_gecB);
    cudaGetSymbolAddress(&p_gecC, g_gecC);
    float* dh = (float*)p_h;

    struct Layer {
        const float *Wl, *bl, *Wr, *pw;
        const int *src, *dst, *gec;   // this layer's edges
        int fixed;
        int *nsrc, *ndst, *ngec;      // next layer's edges
        int n_in, n_per, k;
        float* pool_out;
    } layers[3] = {
        {Wl1, bl1, Wr1, pw1, ei,           ei + NE,      nullptr,       1,
         (int*)p_srcB, (int*)p_dstB, (int*)p_gecB, NN,      NPG, K1, (float*)p_p1},
        {Wl2, bl2, Wr2, pw2, (int*)p_srcB, (int*)p_dstB, (int*)p_gecB,  0,
         (int*)p_srcC, (int*)p_dstC, (int*)p_gecC, NB * K1, K1,  K2, (float*)p_p2},
        {Wl3, bl3, Wr3, pw3, (int*)p_srcC, (int*)p_dstC, (int*)p_gecC,  0,
         nullptr, nullptr, nullptr,                  NB * K2, K2,  K3, (float*)p_p1},
    };

    const float* xin = x;
    for (int l = 0; l < 3; l++) {
        const Layer& L = layers[l];
        int n = L.n_in;

        k_aggregate<<<NB, 1024, AGG_SMEM>>>(L.src, L.dst, L.gec, L.fixed, xin, L.n_per);

        int ntiles = (n + TM - 1) / TM;
        int grid = ntiles < 148 ? ntiles : 148;
        k_sage<<<grid, 256, SAGE_SMEM>>>(xin, L.Wl, L.bl, L.Wr, dh, n);

        k_pool_all<<<NB, 512>>>(dh, L.pw, L.n_per, L.k, l,
                                L.src, L.dst, L.gec, L.fixed,
                                L.nsrc, L.ndst, L.ngec, L.pool_out);

        xin = L.pool_out;
    }

    k_mlp<<<NB, 256>>>(W1, b1, W2, b2, W3, b3, out);
}